// round 1
// baseline (speedup 1.0000x reference)
#include <cuda_runtime.h>
#include <math.h>

// ---------------- problem constants ----------------
namespace {
constexpr int Bn    = 16;
constexpr int E     = 768;
constexpr int HEADS = 12;
constexpr int Ll    = 12;
constexpr int MLPD  = 3072;
constexpr int OUTD  = 2048;
constexpr int PW    = 42;
constexpr int NPAT  = 168;   // 4*42
constexpr int SEQ   = 169;
constexpr int Nrow  = 2704;  // 16*169
constexpr int DH    = 64;
constexpr int E3    = 2304;
constexpr int E2    = 1536;
}

// ---------------- scratch (static device globals; no allocation) ------------
__device__ __align__(16) float g_X   [Nrow * E];
__device__ __align__(16) float g_XN  [Nrow * E];
__device__ __align__(16) float g_QKV [Nrow * E3];
__device__ __align__(16) float g_O   [Nrow * E];
__device__ __align__(16) float g_H1  [Nrow * MLPD];   // also reused for bridge hidden (N*1536)
__device__ __align__(16) float g_PT  [Bn * NPAT * E]; // patchified pixels 2688x768
__device__ __align__(16) float g_PE  [Bn * NPAT * E];
__device__ __align__(16) float g_OUTP[Nrow * OUTD];

// ---------------- patchify: [B,3,64,672] -> [2688, 768] ----------------
__global__ void patchify_kernel(const float* __restrict__ px, float* __restrict__ PT)
{
    int idx = blockIdx.x * blockDim.x + threadIdx.x;
    if (idx >= Bn * NPAT * E) return;
    int k = idx % E;         // c*256 + i*16 + j
    int m = idx / E;
    int b = m / NPAT, p = m % NPAT;
    int ph = p / PW, pw = p % PW;
    int c  = k >> 8;
    int r  = k & 255;
    int ii = r >> 4, jj = r & 15;
    PT[idx] = px[(((size_t)(b * 3 + c) * 64 + ph * 16 + ii) * 672) + pw * 16 + jj];
}

// ---------------- assemble packed sequence with CLS + 2D pos embed ----------
__global__ void assemble_kernel(const float* __restrict__ PE_, const float* __restrict__ cls,
                                const float* __restrict__ row_emb, const float* __restrict__ col_emb,
                                float* __restrict__ X)
{
    int idx = blockIdx.x * blockDim.x + threadIdx.x;
    if (idx >= Nrow * E) return;
    int e = idx % E;
    int n = idx / E;
    int b = n / SEQ, s = n % SEQ;
    float v;
    if (s == 0) {
        v = cls[e];
    } else {
        int p = s - 1, ph = p / PW, pw = p % PW;
        float pos = (e < 384) ? row_emb[ph * 384 + e] : col_emb[pw * 384 + (e - 384)];
        v = PE_[((size_t)(b * NPAT) + p) * E + e] + pos;
    }
    X[idx] = v;
}

// ---------------- LayerNorm: one block per row ----------------
__global__ void ln_kernel(const float* __restrict__ x, const float* __restrict__ g,
                          const float* __restrict__ b, float* __restrict__ y, int D)
{
    int row = blockIdx.x;
    const float* xr = x + (size_t)row * D;
    float s = 0.f, s2 = 0.f;
    for (int i = threadIdx.x; i < D; i += blockDim.x) {
        float v = xr[i];
        s += v; s2 += v * v;
    }
    __shared__ float shs[8], shs2[8];
    #pragma unroll
    for (int o = 16; o; o >>= 1) {
        s  += __shfl_xor_sync(~0u, s,  o);
        s2 += __shfl_xor_sync(~0u, s2, o);
    }
    int w = threadIdx.x >> 5, lane = threadIdx.x & 31;
    if (lane == 0) { shs[w] = s; shs2[w] = s2; }
    __syncthreads();
    if (w == 0) {
        s  = lane < 8 ? shs[lane]  : 0.f;
        s2 = lane < 8 ? shs2[lane] : 0.f;
        #pragma unroll
        for (int o = 4; o; o >>= 1) {
            s  += __shfl_xor_sync(~0u, s,  o);
            s2 += __shfl_xor_sync(~0u, s2, o);
        }
        if (lane == 0) { shs[0] = s; shs2[0] = s2; }
    }
    __syncthreads();
    float m   = shs[0] / (float)D;
    float var = shs2[0] / (float)D - m * m;
    float inv = rsqrtf(var + 1e-5f);
    float* yr = y + (size_t)row * D;
    for (int i = threadIdx.x; i < D; i += blockDim.x)
        yr[i] = (xr[i] - m) * inv * g[i] + b[i];
}

// ---------------- SGEMM: C[M,Nout] = A[M,K] @ W[Nout,K]^T + bias ; epilogues -
// epi: 0 = none, 1 = exact GELU, 2 = residual add (v += Res[row,col])
// Requirements: K % 8 == 0, Nout % 128 == 0 (true for all calls). M edge guarded.
__global__ __launch_bounds__(256) void sgemm_nt(const float* __restrict__ A,
                                                const float* __restrict__ W,
                                                const float* __restrict__ bias,
                                                const float* __restrict__ Res,
                                                float* __restrict__ C,
                                                int M, int K, int Nout, int epi)
{
    __shared__ __align__(16) float As[8][128];
    __shared__ __align__(16) float Bs[8][128];

    const int t  = threadIdx.x;
    const int ar = t >> 1;
    const int ac = (t & 1) * 4;
    const int tx = t & 15, ty = t >> 4;

    const int growA = blockIdx.y * 128 + ar;
    const int growW = blockIdx.x * 128 + ar;
    const bool aval = growA < M;
    const float* Ap = A + (size_t)(aval ? growA : 0) * K + ac;
    const float* Wp = W + (size_t)growW * K + ac;

    float acc[8][8];
    #pragma unroll
    for (int i = 0; i < 8; i++)
        #pragma unroll
        for (int j = 0; j < 8; j++) acc[i][j] = 0.f;

    for (int k0 = 0; k0 < K; k0 += 8) {
        float4 av = aval ? *(const float4*)(Ap + k0) : make_float4(0.f, 0.f, 0.f, 0.f);
        float4 wv = *(const float4*)(Wp + k0);
        As[ac + 0][ar] = av.x; As[ac + 1][ar] = av.y; As[ac + 2][ar] = av.z; As[ac + 3][ar] = av.w;
        Bs[ac + 0][ar] = wv.x; Bs[ac + 1][ar] = wv.y; Bs[ac + 2][ar] = wv.z; Bs[ac + 3][ar] = wv.w;
        __syncthreads();
        #pragma unroll
        for (int kk = 0; kk < 8; kk++) {
            float4 a0 = *(const float4*)&As[kk][ty * 8];
            float4 a1 = *(const float4*)&As[kk][ty * 8 + 4];
            float4 b0 = *(const float4*)&Bs[kk][tx * 8];
            float4 b1 = *(const float4*)&Bs[kk][tx * 8 + 4];
            float a[8] = {a0.x, a0.y, a0.z, a0.w, a1.x, a1.y, a1.z, a1.w};
            float bb[8] = {b0.x, b0.y, b0.z, b0.w, b1.x, b1.y, b1.z, b1.w};
            #pragma unroll
            for (int i = 0; i < 8; i++)
                #pragma unroll
                for (int j = 0; j < 8; j++)
                    acc[i][j] = fmaf(a[i], bb[j], acc[i][j]);
        }
        __syncthreads();
    }

    int row0 = blockIdx.y * 128 + ty * 8;
    int col0 = blockIdx.x * 128 + tx * 8;
    #pragma unroll
    for (int i = 0; i < 8; i++) {
        int r = row0 + i;
        if (r >= M) break;
        size_t off = (size_t)r * Nout + col0;
        #pragma unroll
        for (int j = 0; j < 8; j++) {
            float v = acc[i][j] + bias[col0 + j];
            if (epi == 1)      v = 0.5f * v * (1.0f + erff(v * 0.70710678118654752f));
            else if (epi == 2) v += Res[off + j];
            C[off + j] = v;
        }
    }
}

// ---------------- fused block-diagonal attention ----------------
// grid = B*HEADS blocks, 256 threads (8 warps). Per block: one (image, head).
// smem: Kt[DH][SEQ] (transposed K, conflict-free), Vs[SEQ][DH], S[8][SEQ], Q[8][DH]
constexpr int ATTN_SMEM = (SEQ * DH * 2 + 8 * SEQ + 8 * DH) * 4; // 93,984 B

__global__ __launch_bounds__(256) void attn_kernel(const float* __restrict__ QKV,
                                                   float* __restrict__ Out)
{
    extern __shared__ float sm[];
    float* Kt = sm;                 // DH*SEQ
    float* Vs = Kt + DH * SEQ;      // SEQ*DH
    float* Sb = Vs + SEQ * DH;      // 8*SEQ
    float* Qb = Sb + 8 * SEQ;       // 8*DH

    int bh = blockIdx.x;
    int b = bh / HEADS, h = bh % HEADS;
    int base = b * SEQ;
    int qoff = h * DH, koff = E + h * DH, voff = 2 * E + h * DH;

    for (int idx = threadIdx.x; idx < SEQ * DH; idx += 256) {
        int j = idx >> 6, d = idx & 63;
        size_t rb = (size_t)(base + j) * E3;
        Kt[d * SEQ + j] = QKV[rb + koff + d];
        Vs[idx]         = QKV[rb + voff + d];
    }
    __syncthreads();

    int w = threadIdx.x >> 5, lane = threadIdx.x & 31;
    float* S = Sb + w * SEQ;
    float* Q = Qb + w * DH;

    for (int i = w; i < SEQ; i += 8) {
        const float* qp = QKV + (size_t)(base + i) * E3 + qoff;
        Q[lane]      = qp[lane];
        Q[lane + 32] = qp[lane + 32];
        __syncwarp();

        // scores: each lane owns j = jj*32 + lane (jj=0..5; last partially OOB, discarded)
        float sv[6];
        #pragma unroll
        for (int jj = 0; jj < 6; jj++) sv[jj] = 0.f;
        #pragma unroll 8
        for (int d = 0; d < DH; d++) {
            float qd = Q[d];
            const float* kr = Kt + d * SEQ;
            #pragma unroll
            for (int jj = 0; jj < 6; jj++)
                sv[jj] = fmaf(qd, kr[jj * 32 + lane], sv[jj]); // OOB reads stay in smem, unused
        }

        float mx = -3.0e38f;
        #pragma unroll
        for (int jj = 0; jj < 6; jj++) {
            int j = jj * 32 + lane;
            if (j < SEQ) { sv[jj] *= 0.125f; mx = fmaxf(mx, sv[jj]); }
        }
        #pragma unroll
        for (int o = 16; o; o >>= 1) mx = fmaxf(mx, __shfl_xor_sync(~0u, mx, o));

        float sum = 0.f;
        #pragma unroll
        for (int jj = 0; jj < 6; jj++) {
            int j = jj * 32 + lane;
            if (j < SEQ) { float e = __expf(sv[jj] - mx); S[j] = e; sum += e; }
        }
        #pragma unroll
        for (int o = 16; o; o >>= 1) sum += __shfl_xor_sync(~0u, sum, o);
        float inv = 1.0f / sum;
        __syncwarp();

        float o0 = 0.f, o1 = 0.f;
        for (int j = 0; j < SEQ; j++) {
            float p = S[j];
            o0 = fmaf(p, Vs[j * 64 + lane],      o0);
            o1 = fmaf(p, Vs[j * 64 + lane + 32], o1);
        }
        float* op = Out + (size_t)(base + i) * E + qoff;
        op[lane]      = o0 * inv;
        op[lane + 32] = o1 * inv;
        __syncwarp();
    }
}

// ---------------- vis_mask fill ----------------
__global__ void fill_ones_kernel(float* p, int n)
{
    int i = blockIdx.x * blockDim.x + threadIdx.x;
    if (i < n) p[i] = 1.0f;
}

// ---------------- host orchestration ----------------
extern "C" void kernel_launch(void* const* d_in, const int* in_sizes, int n_in,
                              void* d_out, int out_size)
{
    const float* pixel   = (const float*)d_in[0];
    const float* patch_W = (const float*)d_in[1];
    const float* patch_b = (const float*)d_in[2];
    const float* row_emb = (const float*)d_in[3];
    const float* col_emb = (const float*)d_in[4];
    const float* cls     = (const float*)d_in[5];
    const float* ln1_g   = (const float*)d_in[6];
    const float* ln1_b   = (const float*)d_in[7];
    const float* in_w    = (const float*)d_in[8];
    const float* in_b    = (const float*)d_in[9];
    const float* out_w   = (const float*)d_in[10];
    const float* out_b   = (const float*)d_in[11];
    const float* ln2_g   = (const float*)d_in[12];
    const float* ln2_b   = (const float*)d_in[13];
    const float* mlp_w1  = (const float*)d_in[14];
    const float* mlp_b1  = (const float*)d_in[15];
    const float* mlp_w2  = (const float*)d_in[16];
    const float* mlp_b2  = (const float*)d_in[17];
    const float* fin_g   = (const float*)d_in[18];
    const float* fin_b   = (const float*)d_in[19];
    const float* br_w1   = (const float*)d_in[20];
    const float* br_b1   = (const float*)d_in[21];
    const float* br_w2   = (const float*)d_in[22];
    const float* br_b2   = (const float*)d_in[23];
    const float* br_g    = (const float*)d_in[24];
    const float* br_b    = (const float*)d_in[25];

    float *X, *XN, *QKV, *O, *H1, *PT, *PE, *OUTP;
    cudaGetSymbolAddress((void**)&X,    g_X);
    cudaGetSymbolAddress((void**)&XN,   g_XN);
    cudaGetSymbolAddress((void**)&QKV,  g_QKV);
    cudaGetSymbolAddress((void**)&O,    g_O);
    cudaGetSymbolAddress((void**)&H1,   g_H1);
    cudaGetSymbolAddress((void**)&PT,   g_PT);
    cudaGetSymbolAddress((void**)&PE,   g_PE);
    cudaGetSymbolAddress((void**)&OUTP, g_OUTP);

    cudaFuncSetAttribute(attn_kernel, cudaFuncAttributeMaxDynamicSharedMemorySize, ATTN_SMEM);

    const int MPAT = Bn * NPAT;                 // 2688
    const dim3 blk(256);

    // ---- patch embedding ----
    patchify_kernel<<<(MPAT * E + 255) / 256, blk>>>(pixel, PT);
    sgemm_nt<<<dim3(E / 128, (MPAT + 127) / 128), blk>>>(PT, patch_W, patch_b, nullptr, PE,
                                                         MPAT, E, E, 0);
    assemble_kernel<<<(Nrow * E + 255) / 256, blk>>>(PE, cls, row_emb, col_emb, X);

    const int GY = (Nrow + 127) / 128;          // 22

    // ---- transformer layers ----
    for (int l = 0; l < Ll; l++) {
        ln_kernel<<<Nrow, blk>>>(X, ln1_g + l * E, ln1_b + l * E, XN, E);
        sgemm_nt<<<dim3(E3 / 128, GY), blk>>>(XN, in_w + (size_t)l * E3 * E, in_b + (size_t)l * E3,
                                              nullptr, QKV, Nrow, E, E3, 0);
        attn_kernel<<<Bn * HEADS, blk, ATTN_SMEM>>>(QKV, O);
        sgemm_nt<<<dim3(E / 128, GY), blk>>>(O, out_w + (size_t)l * E * E, out_b + (size_t)l * E,
                                             X, X, Nrow, E, E, 2);
        ln_kernel<<<Nrow, blk>>>(X, ln2_g + l * E, ln2_b + l * E, XN, E);
        sgemm_nt<<<dim3(MLPD / 128, GY), blk>>>(XN, mlp_w1 + (size_t)l * MLPD * E, mlp_b1 + (size_t)l * MLPD,
                                                nullptr, H1, Nrow, E, MLPD, 1);
        sgemm_nt<<<dim3(E / 128, GY), blk>>>(H1, mlp_w2 + (size_t)l * E * MLPD, mlp_b2 + (size_t)l * E,
                                             X, X, Nrow, MLPD, E, 2);
    }

    // ---- final LN + bridge ----
    ln_kernel<<<Nrow, blk>>>(X, fin_g, fin_b, XN, E);
    sgemm_nt<<<dim3(E2 / 128, GY), blk>>>(XN, br_w1, br_b1, nullptr, H1, Nrow, E, E2, 1);
    sgemm_nt<<<dim3(OUTD / 128, GY), blk>>>(H1, br_w2, br_b2, nullptr, OUTP, Nrow, E2, OUTD, 0);
    ln_kernel<<<Nrow, blk>>>(OUTP, br_g, br_b, (float*)d_out, OUTD);

    // ---- vis_mask (ones) if the output buffer carries the second tuple element ----
    long long mainN = (long long)Nrow * OUTD;
    if ((long long)out_size > mainN) {
        int extra = (int)((long long)out_size - mainN);
        fill_ones_kernel<<<(extra + 255) / 256, blk>>>((float*)d_out + mainN, extra);
    }
}

// round 2
// speedup vs baseline: 2.3982x; 2.3982x over previous
#include <cuda_runtime.h>
#include <math.h>
#include <stdint.h>

// ---------------- problem constants ----------------
namespace {
constexpr int Bn    = 16;
constexpr int E     = 768;
constexpr int HEADS = 12;
constexpr int Ll    = 12;
constexpr int MLPD  = 3072;
constexpr int OUTD  = 2048;
constexpr int PW    = 42;
constexpr int NPAT  = 168;
constexpr int SEQ   = 169;
constexpr int Nrow  = 2704;
constexpr int DH    = 64;
constexpr int E3    = 2304;
constexpr int E2    = 1536;
}

// ---------------- scratch ----------------
__device__ __align__(16) float g_X   [Nrow * E];
__device__ __align__(16) float g_XN  [Nrow * E];
__device__ __align__(16) float g_QKV [Nrow * E3];
__device__ __align__(16) float g_O   [Nrow * E];
__device__ __align__(16) float g_H1  [Nrow * MLPD];
__device__ __align__(16) float g_PT  [Bn * NPAT * E];
__device__ __align__(16) float g_PE  [Bn * NPAT * E];
__device__ __align__(16) float g_OUTP[Nrow * OUTD];

// ---------------- patchify ----------------
__global__ void patchify_kernel(const float* __restrict__ px, float* __restrict__ PT)
{
    int idx = blockIdx.x * blockDim.x + threadIdx.x;
    if (idx >= Bn * NPAT * E) return;
    int k = idx % E;
    int m = idx / E;
    int b = m / NPAT, p = m % NPAT;
    int ph = p / PW, pw = p % PW;
    int c  = k >> 8;
    int r  = k & 255;
    int ii = r >> 4, jj = r & 15;
    PT[idx] = px[(((size_t)(b * 3 + c) * 64 + ph * 16 + ii) * 672) + pw * 16 + jj];
}

// ---------------- assemble ----------------
__global__ void assemble_kernel(const float* __restrict__ PE_, const float* __restrict__ cls,
                                const float* __restrict__ row_emb, const float* __restrict__ col_emb,
                                float* __restrict__ X)
{
    int idx = blockIdx.x * blockDim.x + threadIdx.x;
    if (idx >= Nrow * E) return;
    int e = idx % E;
    int n = idx / E;
    int b = n / SEQ, s = n % SEQ;
    float v;
    if (s == 0) {
        v = cls[e];
    } else {
        int p = s - 1, ph = p / PW, pw = p % PW;
        float pos = (e < 384) ? row_emb[ph * 384 + e] : col_emb[pw * 384 + (e - 384)];
        v = PE_[((size_t)(b * NPAT) + p) * E + e] + pos;
    }
    X[idx] = v;
}

// ---------------- LayerNorm ----------------
__global__ void ln_kernel(const float* __restrict__ x, const float* __restrict__ g,
                          const float* __restrict__ b, float* __restrict__ y, int D)
{
    int row = blockIdx.x;
    const float* xr = x + (size_t)row * D;
    float s = 0.f, s2 = 0.f;
    for (int i = threadIdx.x; i < D; i += blockDim.x) {
        float v = xr[i];
        s += v; s2 += v * v;
    }
    __shared__ float shs[8], shs2[8];
    #pragma unroll
    for (int o = 16; o; o >>= 1) {
        s  += __shfl_xor_sync(~0u, s,  o);
        s2 += __shfl_xor_sync(~0u, s2, o);
    }
    int w = threadIdx.x >> 5, lane = threadIdx.x & 31;
    if (lane == 0) { shs[w] = s; shs2[w] = s2; }
    __syncthreads();
    if (w == 0) {
        s  = lane < 8 ? shs[lane]  : 0.f;
        s2 = lane < 8 ? shs2[lane] : 0.f;
        #pragma unroll
        for (int o = 4; o; o >>= 1) {
            s  += __shfl_xor_sync(~0u, s,  o);
            s2 += __shfl_xor_sync(~0u, s2, o);
        }
        if (lane == 0) { shs[0] = s; shs2[0] = s2; }
    }
    __syncthreads();
    float m   = shs[0] / (float)D;
    float var = shs2[0] / (float)D - m * m;
    float inv = rsqrtf(var + 1e-5f);
    float* yr = y + (size_t)row * D;
    for (int i = threadIdx.x; i < D; i += blockDim.x)
        yr[i] = (xr[i] - m) * inv * g[i] + b[i];
}

// ---------------- tf32 helpers ----------------
__device__ __forceinline__ uint32_t f2tf(float f)
{
    uint32_t r;
    asm("cvt.rna.tf32.f32 %0, %1;" : "=r"(r) : "f"(f));
    return r;
}

__device__ __forceinline__ void mma_tf32(float* c, const uint32_t* a, const uint32_t* b)
{
    asm volatile(
        "mma.sync.aligned.m16n8k8.row.col.f32.tf32.tf32.f32 "
        "{%0,%1,%2,%3}, {%4,%5,%6,%7}, {%8,%9}, {%0,%1,%2,%3};\n"
        : "+f"(c[0]), "+f"(c[1]), "+f"(c[2]), "+f"(c[3])
        : "r"(a[0]), "r"(a[1]), "r"(a[2]), "r"(a[3]), "r"(b[0]), "r"(b[1]));
}

// ---------------- TF32 tensor-core GEMM ----------------
// C[M,Nout] = A[M,K] @ W[Nout,K]^T + bias ; epi: 0 none, 1 GELU, 2 residual add.
// K % 16 == 0, Nout % 128 == 0. M edge guarded (A row reads clamped, stores guarded).
// Block tile 128x128, BK=16 double-buffered, 8 warps of 32x64 (m16n8k8 frags).
constexpr int SK = 20;  // smem row stride (floats), conflict-free & 16B aligned

__global__ __launch_bounds__(256) void gemm_tc(const float* __restrict__ A,
                                               const float* __restrict__ W,
                                               const float* __restrict__ bias,
                                               const float* __restrict__ Res,
                                               float* __restrict__ C,
                                               int M, int K, int Nout, int epi)
{
    __shared__ __align__(16) uint32_t As[2][128 * SK];
    __shared__ __align__(16) uint32_t Bs[2][128 * SK];

    const int t = threadIdx.x;
    const int warp = t >> 5, lane = t & 31;
    const int g = lane >> 2, q = lane & 3;
    const int warpM = (warp >> 1) * 32;
    const int warpN = (warp & 1) * 64;

    const int lrow = t >> 1;              // 0..127
    const int kh   = (t & 1) * 8;         // 0 or 8
    int rowA = blockIdx.y * 128 + lrow;
    int rowW = blockIdx.x * 128 + lrow;
    if (rowA >= M) rowA = M - 1;          // clamp (stores are guarded)
    const float* Ap = A + (size_t)rowA * K + kh;
    const float* Wp = W + (size_t)rowW * K + kh;
    const int sbase = lrow * SK + kh;

    float acc[2][8][4];
    #pragma unroll
    for (int mt = 0; mt < 2; mt++)
        #pragma unroll
        for (int nt = 0; nt < 8; nt++)
            #pragma unroll
            for (int i = 0; i < 4; i++) acc[mt][nt][i] = 0.f;

    const int nk = K >> 4;

    // prologue: stage 0
    {
        float4 a0 = *(const float4*)(Ap);
        float4 a1 = *(const float4*)(Ap + 4);
        float4 w0 = *(const float4*)(Wp);
        float4 w1 = *(const float4*)(Wp + 4);
        uint4 ca0 = make_uint4(f2tf(a0.x), f2tf(a0.y), f2tf(a0.z), f2tf(a0.w));
        uint4 ca1 = make_uint4(f2tf(a1.x), f2tf(a1.y), f2tf(a1.z), f2tf(a1.w));
        uint4 cw0 = make_uint4(f2tf(w0.x), f2tf(w0.y), f2tf(w0.z), f2tf(w0.w));
        uint4 cw1 = make_uint4(f2tf(w1.x), f2tf(w1.y), f2tf(w1.z), f2tf(w1.w));
        *(uint4*)&As[0][sbase]     = ca0;
        *(uint4*)&As[0][sbase + 4] = ca1;
        *(uint4*)&Bs[0][sbase]     = cw0;
        *(uint4*)&Bs[0][sbase + 4] = cw1;
    }
    __syncthreads();

    for (int kb = 0; kb < nk; kb++) {
        // prefetch next K-slab from global
        float4 pa0, pa1, pw0, pw1;
        const bool more = (kb + 1) < nk;
        if (more) {
            const float* An = Ap + (kb + 1) * 16;
            const float* Wn = Wp + (kb + 1) * 16;
            pa0 = *(const float4*)(An);
            pa1 = *(const float4*)(An + 4);
            pw0 = *(const float4*)(Wn);
            pw1 = *(const float4*)(Wn + 4);
        }

        // compute current stage
        const uint32_t* as = As[kb & 1];
        const uint32_t* bs = Bs[kb & 1];
        #pragma unroll
        for (int ks = 0; ks < 2; ks++) {
            const int kq = ks * 8 + q;
            uint32_t af[2][4];
            uint32_t bf[8][2];
            #pragma unroll
            for (int mt = 0; mt < 2; mt++) {
                const int r = warpM + mt * 16;
                af[mt][0] = as[(r + g) * SK + kq];
                af[mt][1] = as[(r + g + 8) * SK + kq];
                af[mt][2] = as[(r + g) * SK + kq + 4];
                af[mt][3] = as[(r + g + 8) * SK + kq + 4];
            }
            #pragma unroll
            for (int nt = 0; nt < 8; nt++) {
                const int n = warpN + nt * 8 + g;
                bf[nt][0] = bs[n * SK + kq];
                bf[nt][1] = bs[n * SK + kq + 4];
            }
            #pragma unroll
            for (int mt = 0; mt < 2; mt++)
                #pragma unroll
                for (int nt = 0; nt < 8; nt++)
                    mma_tf32(acc[mt][nt], af[mt], bf[nt]);
        }

        if (more) {
            uint32_t* asn = As[(kb + 1) & 1];
            uint32_t* bsn = Bs[(kb + 1) & 1];
            uint4 ca0 = make_uint4(f2tf(pa0.x), f2tf(pa0.y), f2tf(pa0.z), f2tf(pa0.w));
            uint4 ca1 = make_uint4(f2tf(pa1.x), f2tf(pa1.y), f2tf(pa1.z), f2tf(pa1.w));
            uint4 cw0 = make_uint4(f2tf(pw0.x), f2tf(pw0.y), f2tf(pw0.z), f2tf(pw0.w));
            uint4 cw1 = make_uint4(f2tf(pw1.x), f2tf(pw1.y), f2tf(pw1.z), f2tf(pw1.w));
            *(uint4*)&asn[sbase]     = ca0;
            *(uint4*)&asn[sbase + 4] = ca1;
            *(uint4*)&bsn[sbase]     = cw0;
            *(uint4*)&bsn[sbase + 4] = cw1;
        }
        __syncthreads();
    }

    // epilogue
    #pragma unroll
    for (int mt = 0; mt < 2; mt++) {
        #pragma unroll
        for (int half = 0; half < 2; half++) {
            const int r = blockIdx.y * 128 + warpM + mt * 16 + g + half * 8;
            if (r >= M) continue;
            const size_t off = (size_t)r * Nout;
            #pragma unroll
            for (int nt = 0; nt < 8; nt++) {
                const int c = blockIdx.x * 128 + warpN + nt * 8 + q * 2;
                float v0 = acc[mt][nt][half * 2 + 0] + bias[c];
                float v1 = acc[mt][nt][half * 2 + 1] + bias[c + 1];
                if (epi == 1) {
                    v0 = 0.5f * v0 * (1.0f + erff(v0 * 0.70710678118654752f));
                    v1 = 0.5f * v1 * (1.0f + erff(v1 * 0.70710678118654752f));
                } else if (epi == 2) {
                    v0 += Res[off + c];
                    v1 += Res[off + c + 1];
                }
                *(float2*)(C + off + c) = make_float2(v0, v1);
            }
        }
    }
}

// ---------------- fused block-diagonal attention ----------------
constexpr int ATTN_SMEM = (SEQ * DH * 2 + 8 * SEQ + 8 * DH) * 4;

__global__ __launch_bounds__(256) void attn_kernel(const float* __restrict__ QKV,
                                                   float* __restrict__ Out)
{
    extern __shared__ float sm[];
    float* Kt = sm;
    float* Vs = Kt + DH * SEQ;
    float* Sb = Vs + SEQ * DH;
    float* Qb = Sb + 8 * SEQ;

    int bh = blockIdx.x;
    int b = bh / HEADS, h = bh % HEADS;
    int base = b * SEQ;
    int qoff = h * DH, koff = E + h * DH, voff = 2 * E + h * DH;

    for (int idx = threadIdx.x; idx < SEQ * DH; idx += 256) {
        int j = idx >> 6, d = idx & 63;
        size_t rb = (size_t)(base + j) * E3;
        Kt[d * SEQ + j] = QKV[rb + koff + d];
        Vs[idx]         = QKV[rb + voff + d];
    }
    __syncthreads();

    int w = threadIdx.x >> 5, lane = threadIdx.x & 31;
    float* S = Sb + w * SEQ;
    float* Q = Qb + w * DH;

    for (int i = w; i < SEQ; i += 8) {
        const float* qp = QKV + (size_t)(base + i) * E3 + qoff;
        Q[lane]      = qp[lane];
        Q[lane + 32] = qp[lane + 32];
        __syncwarp();

        float sv[6];
        #pragma unroll
        for (int jj = 0; jj < 6; jj++) sv[jj] = 0.f;
        #pragma unroll 8
        for (int d = 0; d < DH; d++) {
            float qd = Q[d];
            const float* kr = Kt + d * SEQ;
            #pragma unroll
            for (int jj = 0; jj < 6; jj++)
                sv[jj] = fmaf(qd, kr[jj * 32 + lane], sv[jj]);
        }

        float mx = -3.0e38f;
        #pragma unroll
        for (int jj = 0; jj < 6; jj++) {
            int j = jj * 32 + lane;
            if (j < SEQ) { sv[jj] *= 0.125f; mx = fmaxf(mx, sv[jj]); }
        }
        #pragma unroll
        for (int o = 16; o; o >>= 1) mx = fmaxf(mx, __shfl_xor_sync(~0u, mx, o));

        float sum = 0.f;
        #pragma unroll
        for (int jj = 0; jj < 6; jj++) {
            int j = jj * 32 + lane;
            if (j < SEQ) { float e = __expf(sv[jj] - mx); S[j] = e; sum += e; }
        }
        #pragma unroll
        for (int o = 16; o; o >>= 1) sum += __shfl_xor_sync(~0u, sum, o);
        float inv = 1.0f / sum;
        __syncwarp();

        float o0 = 0.f, o1 = 0.f;
        for (int j = 0; j < SEQ; j++) {
            float p = S[j];
            o0 = fmaf(p, Vs[j * 64 + lane],      o0);
            o1 = fmaf(p, Vs[j * 64 + lane + 32], o1);
        }
        float* op = Out + (size_t)(base + i) * E + qoff;
        op[lane]      = o0 * inv;
        op[lane + 32] = o1 * inv;
        __syncwarp();
    }
}

__global__ void fill_ones_kernel(float* p, int n)
{
    int i = blockIdx.x * blockDim.x + threadIdx.x;
    if (i < n) p[i] = 1.0f;
}

// ---------------- host orchestration ----------------
extern "C" void kernel_launch(void* const* d_in, const int* in_sizes, int n_in,
                              void* d_out, int out_size)
{
    const float* pixel   = (const float*)d_in[0];
    const float* patch_W = (const float*)d_in[1];
    const float* patch_b = (const float*)d_in[2];
    const float* row_emb = (const float*)d_in[3];
    const float* col_emb = (const float*)d_in[4];
    const float* cls     = (const float*)d_in[5];
    const float* ln1_g   = (const float*)d_in[6];
    const float* ln1_b   = (const float*)d_in[7];
    const float* in_w    = (const float*)d_in[8];
    const float* in_b    = (const float*)d_in[9];
    const float* out_w   = (const float*)d_in[10];
    const float* out_b   = (const float*)d_in[11];
    const float* ln2_g   = (const float*)d_in[12];
    const float* ln2_b   = (const float*)d_in[13];
    const float* mlp_w1  = (const float*)d_in[14];
    const float* mlp_b1  = (const float*)d_in[15];
    const float* mlp_w2  = (const float*)d_in[16];
    const float* mlp_b2  = (const float*)d_in[17];
    const float* fin_g   = (const float*)d_in[18];
    const float* fin_b   = (const float*)d_in[19];
    const float* br_w1   = (const float*)d_in[20];
    const float* br_b1   = (const float*)d_in[21];
    const float* br_w2   = (const float*)d_in[22];
    const float* br_b2   = (const float*)d_in[23];
    const float* br_g    = (const float*)d_in[24];
    const float* br_b    = (const float*)d_in[25];

    float *X, *XN, *QKV, *O, *H1, *PT, *PE, *OUTP;
    cudaGetSymbolAddress((void**)&X,    g_X);
    cudaGetSymbolAddress((void**)&XN,   g_XN);
    cudaGetSymbolAddress((void**)&QKV,  g_QKV);
    cudaGetSymbolAddress((void**)&O,    g_O);
    cudaGetSymbolAddress((void**)&H1,   g_H1);
    cudaGetSymbolAddress((void**)&PT,   g_PT);
    cudaGetSymbolAddress((void**)&PE,   g_PE);
    cudaGetSymbolAddress((void**)&OUTP, g_OUTP);

    cudaFuncSetAttribute(attn_kernel, cudaFuncAttributeMaxDynamicSharedMemorySize, ATTN_SMEM);

    const int MPAT = Bn * NPAT;
    const dim3 blk(256);

    patchify_kernel<<<(MPAT * E + 255) / 256, blk>>>(pixel, PT);
    gemm_tc<<<dim3(E / 128, (MPAT + 127) / 128), blk>>>(PT, patch_W, patch_b, nullptr, PE,
                                                        MPAT, E, E, 0);
    assemble_kernel<<<(Nrow * E + 255) / 256, blk>>>(PE, cls, row_emb, col_emb, X);

    const int GY = (Nrow + 127) / 128;

    for (int l = 0; l < Ll; l++) {
        ln_kernel<<<Nrow, blk>>>(X, ln1_g + l * E, ln1_b + l * E, XN, E);
        gemm_tc<<<dim3(E3 / 128, GY), blk>>>(XN, in_w + (size_t)l * E3 * E, in_b + (size_t)l * E3,
                                             nullptr, QKV, Nrow, E, E3, 0);
        attn_kernel<<<Bn * HEADS, blk, ATTN_SMEM>>>(QKV, O);
        gemm_tc<<<dim3(E / 128, GY), blk>>>(O, out_w + (size_t)l * E * E, out_b + (size_t)l * E,
                                            X, X, Nrow, E, E, 2);
        ln_kernel<<<Nrow, blk>>>(X, ln2_g + l * E, ln2_b + l * E, XN, E);
        gemm_tc<<<dim3(MLPD / 128, GY), blk>>>(XN, mlp_w1 + (size_t)l * MLPD * E, mlp_b1 + (size_t)l * MLPD,
                                               nullptr, H1, Nrow, E, MLPD, 1);
        gemm_tc<<<dim3(E / 128, GY), blk>>>(H1, mlp_w2 + (size_t)l * E * MLPD, mlp_b2 + (size_t)l * E,
                                            X, X, Nrow, MLPD, E, 2);
    }

    ln_kernel<<<Nrow, blk>>>(X, fin_g, fin_b, XN, E);
    gemm_tc<<<dim3(E2 / 128, GY), blk>>>(XN, br_w1, br_b1, nullptr, H1, Nrow, E, E2, 1);
    gemm_tc<<<dim3(OUTD / 128, GY), blk>>>(H1, br_w2, br_b2, nullptr, OUTP, Nrow, E2, OUTD, 0);
    ln_kernel<<<Nrow, blk>>>(OUTP, br_g, br_b, (float*)d_out, OUTD);

    long long mainN = (long long)Nrow * OUTD;
    if ((long long)out_size > mainN) {
        int extra = (int)((long long)out_size - mainN);
        fill_ones_kernel<<<(extra + 255) / 256, blk>>>((float*)d_out + mainN, extra);
    }
}